// round 15
// baseline (speedup 1.0000x reference)
#include <cuda_runtime.h>
#include <cuda_fp16.h>
#include <cstdint>

#define EPS 1e-6f

// ---------------- device scratch (no allocations allowed) ----------------
__device__ float4 g_params[4096];          // per (b,t): {1+scale, shift, gate, 0}
__device__ int    g_valid[16 * 4096];      // per batch: compacted flat indices
__device__ int    g_count[16];             // per batch: valid count
__device__ __half g_xn_h[4096 * 1024];     // normalized tokens (fp16)
__device__ float  g_featsp[2][4096 * 512]; // GEMM1 partial outputs (K-split)
__device__ __half g_u_h[65536 * 512];      // modulated-silu activations (fp16)
__device__ __half g_cn_h[65536 * 512];     // normalized chars (fp16, compacted)
__device__ __half g_wd_h[512 * 1024];      // W_down fp16
__device__ __half g_wf_h[512 * 512];       // W_fusion fp16

// ---------------- helpers ----------------
__device__ __forceinline__ float tanh_ap(float x) {
    float y;
    asm("tanh.approx.f32 %0, %1;" : "=f"(y) : "f"(x));
    return y;
}
__device__ __forceinline__ float silu_f(float z) {
    return z * (0.5f + 0.5f * tanh_ap(0.5f * z));
}
__device__ __forceinline__ uint32_t smem_u32(const void* p) {
    return (uint32_t)__cvta_generic_to_shared(p);
}
__device__ __forceinline__ void cp16(uint32_t d, const void* s) {
    asm volatile("cp.async.cg.shared.global [%0], [%1], 16;" ::"r"(d), "l"(s));
}
#define CP_COMMIT asm volatile("cp.async.commit_group;")
#define CP_WAIT0 asm volatile("cp.async.wait_group 0;")
#define CP_WAIT1 asm volatile("cp.async.wait_group 1;")

__device__ __forceinline__ void ldsm4(uint32_t& r0, uint32_t& r1, uint32_t& r2,
                                      uint32_t& r3, uint32_t addr) {
    asm volatile("ldmatrix.sync.aligned.m8n8.x4.shared.b16 {%0,%1,%2,%3}, [%4];"
                 : "=r"(r0), "=r"(r1), "=r"(r2), "=r"(r3)
                 : "r"(addr));
}
__device__ __forceinline__ void mma16(float* c, const uint32_t* a, const uint32_t* b) {
    asm volatile(
        "mma.sync.aligned.m16n8k16.row.col.f32.f16.f16.f32 "
        "{%0,%1,%2,%3}, {%4,%5,%6,%7}, {%8,%9}, {%0,%1,%2,%3};"
        : "+f"(c[0]), "+f"(c[1]), "+f"(c[2]), "+f"(c[3])
        : "r"(a[0]), "r"(a[1]), "r"(a[2]), "r"(a[3]), "r"(b[0]), "r"(b[1]));
}

// ---------------- prep bodies (merged launch) ----------------
__device__ void scan_body(const int* __restrict__ mask, int b) {
    int tid = threadIdx.x;
    int warp = tid >> 5, lane = tid & 31;
    __shared__ int wsum[8];
    const int* m = mask + b * 4096 + tid * 16;
    unsigned flags = 0;
    int cnt = 0;
#pragma unroll
    for (int i = 0; i < 16; i++)
        if (m[i] != 0) { flags |= (1u << i); cnt++; }
    int pre = cnt;
#pragma unroll
    for (int o = 1; o < 32; o <<= 1) {
        int v = __shfl_up_sync(0xffffffffu, pre, o);
        if (lane >= o) pre += v;
    }
    if (lane == 31) wsum[warp] = pre;
    __syncthreads();
    if (warp == 0) {
        int v = (lane < 8) ? wsum[lane] : 0;
#pragma unroll
        for (int o = 1; o < 8; o <<= 1) {
            int t = __shfl_up_sync(0xffffffffu, v, o);
            if (lane >= o) v += t;
        }
        if (lane < 8) wsum[lane] = v;
    }
    __syncthreads();
    int base = pre - cnt + (warp ? wsum[warp - 1] : 0);
    int ib = b * 4096;
#pragma unroll
    for (int i = 0; i < 16; i++)
        if (flags & (1u << i)) g_valid[ib + base++] = tid * 16 + i;
    if (tid == 255) g_count[b] = wsum[7];
}

__device__ void cvt_body(const float* __restrict__ Wd, const float* __restrict__ Wf,
                         int blk) {
    int i = blk * 256 + threadIdx.x;
    g_wd_h[i] = __float2half_rn(Wd[i]);
    if (i < 512 * 512) g_wf_h[i] = __float2half_rn(Wf[i]);
}

__device__ void norm_tok_body(const float* __restrict__ tok,
                              const float* __restrict__ w_pre, int blk) {
    int warp = threadIdx.x >> 5, lane = threadIdx.x & 31;
    int row = blk * 8 + warp;
    const float4* x = (const float4*)(tok + (size_t)row * 1024);
    const float4* w = (const float4*)w_pre;
    float4 v[8];
    float ss = 0.f;
#pragma unroll
    for (int i = 0; i < 8; i++) {
        float4 a = __ldcs(&x[lane + 32 * i]);
        v[i] = a;
        ss += a.x * a.x + a.y * a.y + a.z * a.z + a.w * a.w;
    }
#pragma unroll
    for (int o = 16; o >= 1; o >>= 1) ss += __shfl_xor_sync(0xffffffffu, ss, o);
    float inv = rsqrtf(ss * (1.0f / 1024.0f) + EPS);
    __half2* out = (__half2*)(g_xn_h + (size_t)row * 1024);
#pragma unroll
    for (int i = 0; i < 8; i++) {
        float4 ww = w[lane + 32 * i];
        int f4 = lane + 32 * i;
        out[2 * f4] = __floats2half2_rn(v[i].x * inv * ww.x, v[i].y * inv * ww.y);
        out[2 * f4 + 1] = __floats2half2_rn(v[i].z * inv * ww.z, v[i].w * inv * ww.w);
    }
}

// merged launch: blocks [0,16) scan, [16,2064) cvt, [2064,2576) norm_tok
__global__ __launch_bounds__(256) void k_prep(const int* __restrict__ mask,
                                              const float* __restrict__ Wd,
                                              const float* __restrict__ Wf,
                                              const float* __restrict__ tok,
                                              const float* __restrict__ w_pre) {
    int bx = blockIdx.x;
    if (bx < 16) scan_body(mask, bx);
    else if (bx < 2064) cvt_body(Wd, Wf, bx - 16);
    else norm_tok_body(tok, w_pre, bx - 2064);
}

// ---------------- fp16 GEMM core: C(128x128) += A(128xK) @ B(128xK)^T ----------------
// 256 threads = 8 warps (4M x 2N), warp tile 32x64, mma m16n8k16 f16->f32.
// smem: 3-stage ring, k-chunk 64 halfs, row stride 72 halfs (conflict-free ldmatrix).
// 2 chunks in flight (wait_group 1); one __syncthreads per 64-k chunk.
// A-fragment double buffer: ks+1's LDSM issues before ks's 16 HMMA drain.
template <int NC>
__device__ __forceinline__ void gemm_core(const __half* __restrict__ A,
                                          const __half* __restrict__ B, int lda, int ldb,
                                          int rowBase, int nBase, int kOff,
                                          float (&acc)[2][8][4], char* smraw) {
    const int STG_H = 2 * 128 * 72;
    __half* sm = (__half*)smraw;
    int tid = threadIdx.x;
    int wid = tid >> 5, lane = tid & 31;
    int warpM = wid >> 1, warpN = wid & 1;
    int r8 = lane & 7, quad = lane >> 3;

    int lrow = tid & 127;
    bool isB = tid >= 128;
    const __half* gsrc = (isB ? (B + (size_t)(nBase + lrow) * ldb)
                              : (A + (size_t)(rowBase + lrow) * lda)) + kOff;
    uint32_t sdst0 = smem_u32(sm) + (uint32_t)(((isB ? 128 * 72 : 0) + lrow * 72) * 2);

#define STAGE_LD(s, buf)                                                     \
    do {                                                                     \
        const __half* gp = gsrc + (s)*64;                                    \
        uint32_t sp = sdst0 + (uint32_t)((buf)*STG_H * 2);                   \
        _Pragma("unroll") for (int j = 0; j < 8; j++) cp16(sp + j * 16, gp + j * 8); \
        CP_COMMIT;                                                           \
    } while (0)

    STAGE_LD(0, 0);
    STAGE_LD(1, 1);

    uint32_t sbase = smem_u32(sm);
    int arow = warpM * 32 + ((quad & 1) << 3) + r8;
    int aco = (quad >> 1) << 3;
    int brow = warpN * 64 + ((quad >> 1) << 3) + r8;
    int bco = (quad & 1) << 3;

    int cur = 0, nxt = 2;
    for (int kc = 0; kc < NC; kc++) {
        if (kc < NC - 1) { CP_WAIT1; }
        else { CP_WAIT0; }
        __syncthreads();
        if (kc + 2 < NC) STAGE_LD(kc + 2, nxt);

        uint32_t stg = sbase + (uint32_t)((cur * STG_H) * 2);
        uint32_t astg = stg, bstg = stg + (uint32_t)(128 * 72 * 2);

        uint32_t af[2][2][4];  // [buf][mt][4] double-buffered A frags
#pragma unroll
        for (int mt = 0; mt < 2; mt++) {
            uint32_t addr = astg + (uint32_t)(((arow + mt * 16) * 72 + aco) * 2);
            ldsm4(af[0][mt][0], af[0][mt][1], af[0][mt][2], af[0][mt][3], addr);
        }
#pragma unroll
        for (int ks = 0; ks < 4; ks++) {
            int k0 = ks * 16;
            if (ks < 3) {
#pragma unroll
                for (int mt = 0; mt < 2; mt++) {
                    uint32_t addr =
                        astg + (uint32_t)(((arow + mt * 16) * 72 + aco + k0 + 16) * 2);
                    ldsm4(af[(ks + 1) & 1][mt][0], af[(ks + 1) & 1][mt][1],
                          af[(ks + 1) & 1][mt][2], af[(ks + 1) & 1][mt][3], addr);
                }
            }
            const uint32_t(*ac)[4] = af[ks & 1];
#pragma unroll
            for (int g16 = 0; g16 < 4; g16++) {
                uint32_t b0, b1, b2, b3;
                uint32_t addr = bstg + (uint32_t)(((brow + g16 * 16) * 72 + bco + k0) * 2);
                ldsm4(b0, b1, b2, b3, addr);
                uint32_t bf0[2] = {b0, b1}, bf1[2] = {b2, b3};
                mma16(acc[0][g16 * 2], ac[0], bf0);
                mma16(acc[0][g16 * 2 + 1], ac[0], bf1);
                mma16(acc[1][g16 * 2], ac[1], bf0);
                mma16(acc[1][g16 * 2 + 1], ac[1], bf1);
            }
        }
        cur = (cur == 2) ? 0 : cur + 1;
        nxt = (nxt == 2) ? 0 : nxt + 1;
    }
#undef STAGE_LD
}

// ---------------- kernel 2: GEMM1 (K-split x2) partials ----------------
__global__ __launch_bounds__(256, 2) void k_gemm1() {
    extern __shared__ char smraw[];
    float acc[2][8][4] = {};
    int split = blockIdx.x & 1;
    int nTile = (blockIdx.x >> 1) & 3;
    int rowTile = blockIdx.x >> 3;
    gemm_core<8>(g_xn_h, g_wd_h, 1024, 1024, rowTile * 128, nTile * 128, split * 512,
                 acc, smraw);
    float* dst = g_featsp[split];
    int tid = threadIdx.x, wid = tid >> 5, lane = tid & 31;
    int warpM = wid >> 1, warpN = wid & 1, g = lane >> 2, qc = lane & 3;
#pragma unroll
    for (int mi = 0; mi < 2; mi++)
#pragma unroll
        for (int ni = 0; ni < 8; ni++) {
            int r = rowTile * 128 + warpM * 32 + mi * 16 + g;
            int c = nTile * 128 + warpN * 64 + ni * 8 + qc * 2;
            float2 v0 = {acc[mi][ni][0], acc[mi][ni][1]};
            float2 v1 = {acc[mi][ni][2], acc[mi][ni][3]};
            *(float2*)(dst + (size_t)r * 512 + c) = v0;
            *(float2*)(dst + (size_t)(r + 8) * 512 + c) = v1;
        }
}

// ---------------- kernel 3: sum partials + rmsnorm + silu + W_proj -> params --------
__global__ __launch_bounds__(256) void k_post(const float* __restrict__ w_tok,
                                              const float* __restrict__ Wp) {
    int warp = threadIdx.x >> 5, lane = threadIdx.x & 31;
    int row = blockIdx.x * 8 + warp;
    const float4* f0 = (const float4*)(g_featsp[0] + (size_t)row * 512);
    const float4* f1 = (const float4*)(g_featsp[1] + (size_t)row * 512);
    float4 v[4];
    float ss = 0.f;
#pragma unroll
    for (int i = 0; i < 4; i++) {
        float4 a = f0[lane + 32 * i];
        float4 b = f1[lane + 32 * i];
        a.x += b.x; a.y += b.y; a.z += b.z; a.w += b.w;
        v[i] = a;
        ss += a.x * a.x + a.y * a.y + a.z * a.z + a.w * a.w;
    }
#pragma unroll
    for (int o = 16; o >= 1; o >>= 1) ss += __shfl_xor_sync(0xffffffffu, ss, o);
    float inv = rsqrtf(ss * (1.0f / 512.0f) + EPS);
    const float4* wt = (const float4*)w_tok;
    const float4* wp0 = (const float4*)Wp;
    const float4* wp1 = (const float4*)(Wp + 512);
    const float4* wp2 = (const float4*)(Wp + 1024);
    float p0 = 0.f, p1 = 0.f, p2 = 0.f;
#pragma unroll
    for (int i = 0; i < 4; i++) {
        float4 ww = wt[lane + 32 * i];
        float4 a = v[i];
        float s0 = silu_f(a.x * inv * ww.x), s1 = silu_f(a.y * inv * ww.y);
        float s2 = silu_f(a.z * inv * ww.z), s3 = silu_f(a.w * inv * ww.w);
        float4 q0 = wp0[lane + 32 * i], q1 = wp1[lane + 32 * i], q2 = wp2[lane + 32 * i];
        p0 += s0 * q0.x + s1 * q0.y + s2 * q0.z + s3 * q0.w;
        p1 += s0 * q1.x + s1 * q1.y + s2 * q1.z + s3 * q1.w;
        p2 += s0 * q2.x + s1 * q2.y + s2 * q2.z + s3 * q2.w;
    }
#pragma unroll
    for (int o = 16; o >= 1; o >>= 1) {
        p0 += __shfl_xor_sync(0xffffffffu, p0, o);
        p1 += __shfl_xor_sync(0xffffffffu, p1, o);
        p2 += __shfl_xor_sync(0xffffffffu, p2, o);
    }
    if (lane == 0) {
        float4 pr;
        pr.x = 1.0f + p0;
        pr.y = p1;
        pr.z = 1.0f / (1.0f + __expf(-p2));
        pr.w = 0.f;
        g_params[row] = pr;
    }
}

// ---------------- kernel 4a: char rmsnorm -> g_cn_h (params-independent) ------------
__global__ __launch_bounds__(256) void k_cn(const float* __restrict__ ch,
                                            const float* __restrict__ w_char) {
    int warp = threadIdx.x >> 5, lane = threadIdx.x & 31;
    int jj = blockIdx.x * 8 + warp;
    int b = jj >> 12, j = jj & 4095;
    if (j >= g_count[b]) return;
    int flat = g_valid[b * 4096 + j];
    const float4* x = (const float4*)(ch + (size_t)(b * 4096 + flat) * 512);
    float4 v[4];
    float ss = 0.f;
#pragma unroll
    for (int i = 0; i < 4; i++) {
        float4 a = __ldcs(&x[lane + 32 * i]);
        v[i] = a;
        ss += a.x * a.x + a.y * a.y + a.z * a.z + a.w * a.w;
    }
#pragma unroll
    for (int o = 16; o >= 1; o >>= 1) ss += __shfl_xor_sync(0xffffffffu, ss, o);
    float inv = rsqrtf(ss * (1.0f / 512.0f) + EPS);
    const float4* w = (const float4*)w_char;
    __half2* co = (__half2*)(g_cn_h + (size_t)(b * 4096 + j) * 512);
#pragma unroll
    for (int i = 0; i < 4; i++) {
        float4 ww = w[lane + 32 * i];
        float4 a = v[i];
        int f4 = lane + 32 * i;
        co[2 * f4] = __floats2half2_rn(a.x * inv * ww.x, a.y * inv * ww.y);
        co[2 * f4 + 1] = __floats2half2_rn(a.z * inv * ww.z, a.w * inv * ww.w);
    }
}

// ---------------- kernel 4b: u = silu(cn * (1+scale) + shift) -> g_u_h --------------
__global__ __launch_bounds__(256) void k_usilu() {
    int warp = threadIdx.x >> 5, lane = threadIdx.x & 31;
    int jj = blockIdx.x * 8 + warp;
    int b = jj >> 12, j = jj & 4095;
    if (j >= g_count[b]) return;
    int flat = g_valid[b * 4096 + j];
    float4 p = g_params[b * 256 + (flat >> 4)];
    const __half2* ci = (const __half2*)(g_cn_h + (size_t)(b * 4096 + j) * 512);
    __half2* uo = (__half2*)(g_u_h + (size_t)(b * 4096 + j) * 512);
#pragma unroll
    for (int i = 0; i < 8; i++) {
        __half2 cv = ci[lane + 32 * i];
        float2 c = __half22float2(cv);
        uo[lane + 32 * i] =
            __floats2half2_rn(silu_f(c.x * p.x + p.y), silu_f(c.y * p.x + p.y));
    }
}

// ---------------- kernel 5: GEMM2 + gated mix + filler epilogue ----------------
__global__ __launch_bounds__(256, 2) void k_gemm_fuse(const float* __restrict__ filler,
                                                      float* __restrict__ out) {
    int rowTile = blockIdx.x >> 2, nTile = blockIdx.x & 3;
    int b = rowTile >> 5, j0 = (rowTile & 31) * 128;
    int cnt = g_count[b];
    int tid = threadIdx.x;

    if (j0 >= cnt) {  // entire tile filler: broadcast
        int f4c = tid & 31, r0 = tid >> 5;
        float4 fv = ((const float4*)filler)[nTile * 32 + f4c];
        float4* ob = (float4*)(out + (size_t)(b * 4096 + j0) * 512 + nTile * 128);
#pragma unroll
        for (int it = 0; it < 16; it++) __stcs(&ob[(size_t)(r0 + 8 * it) * 128 + f4c], fv);
        return;
    }

    extern __shared__ char smraw[];
    float acc[2][8][4] = {};
    gemm_core<8>(g_u_h, g_wf_h, 512, 512, b * 4096 + j0, nTile * 128, 0, acc, smraw);

    int wid = tid >> 5, lane = tid & 31;
    int warpM = wid >> 1, warpN = wid & 1, g = lane >> 2, qc = lane & 3;
    const float2* fil2 = (const float2*)filler;
#pragma unroll
    for (int mi = 0; mi < 2; mi++)
#pragma unroll
        for (int rr = 0; rr < 2; rr++) {
            int lr = warpM * 32 + mi * 16 + g + rr * 8;
            int j = j0 + lr;
            bool val = j < cnt;
            float gate = 0.f;
            if (val) {
                int flat = g_valid[b * 4096 + j];
                gate = g_params[b * 256 + (flat >> 4)].z;
            }
            float og = 1.f - gate;
            const __half2* cnrow = (const __half2*)(g_cn_h + (size_t)(b * 4096 + j) * 512);
            float* orow = out + (size_t)(b * 4096 + j) * 512;
#pragma unroll
            for (int ni = 0; ni < 8; ni++) {
                int c = nTile * 128 + warpN * 64 + ni * 8 + qc * 2;
                float a0 = acc[mi][ni][rr * 2 + 0], a1 = acc[mi][ni][rr * 2 + 1];
                float2 o;
                if (val) {
                    float2 cv = __half22float2(cnrow[c >> 1]);
                    o.x = gate * a0 + og * cv.x;
                    o.y = gate * a1 + og * cv.y;
                } else {
                    o = fil2[c >> 1];
                }
                __stcs((float2*)(orow + c), o);
            }
        }
}

// ---------------- launch ----------------
extern "C" void kernel_launch(void* const* d_in, const int* in_sizes, int n_in,
                              void* d_out, int out_size) {
    (void)in_sizes;
    (void)n_in;
    (void)out_size;
    const float* tok = (const float*)d_in[0];
    const float* ch = (const float*)d_in[2];
    const int* cmask = (const int*)d_in[3];
    const float* filler = (const float*)d_in[4];
    const float* w_pre = (const float*)d_in[5];
    const float* w_tok = (const float*)d_in[6];
    const float* w_char = (const float*)d_in[7];
    const float* Wd = (const float*)d_in[8];
    const float* Wp = (const float*)d_in[9];
    const float* Wf = (const float*)d_in[10];
    float* out = (float*)d_out;

    const int SMEM = 3 * 2 * 128 * 72 * 2;  // 110592 bytes -> 2 CTAs/SM
    cudaFuncSetAttribute(k_gemm1, cudaFuncAttributeMaxDynamicSharedMemorySize, SMEM);
    cudaFuncSetAttribute(k_gemm_fuse, cudaFuncAttributeMaxDynamicSharedMemorySize, SMEM);

    // one-time host-side resources (no device memory involved)
    static cudaStream_t s_side = nullptr;
    static cudaEvent_t ev_fork = nullptr, ev_join = nullptr;
    if (s_side == nullptr) {
        cudaStreamCreateWithFlags(&s_side, cudaStreamNonBlocking);
        cudaEventCreateWithFlags(&ev_fork, cudaEventDisableTiming);
        cudaEventCreateWithFlags(&ev_join, cudaEventDisableTiming);
    }

    k_prep<<<2576, 256>>>(cmask, Wd, Wf, tok, w_pre);

    // fork: k_cn (needs only scan results) runs concurrently with gemm1+post
    cudaEventRecord(ev_fork, 0);
    cudaStreamWaitEvent(s_side, ev_fork, 0);
    k_cn<<<8192, 256, 0, s_side>>>(ch, w_char);
    cudaEventRecord(ev_join, s_side);

    k_gemm1<<<256, 256, SMEM>>>();
    k_post<<<512, 256>>>(w_tok, Wp);

    // join: u = silu(cn*(1+scale)+shift) needs both params and cn
    cudaStreamWaitEvent(0, ev_join, 0);
    k_usilu<<<8192, 256>>>();
    k_gemm_fuse<<<2048, 256, SMEM>>>(filler, out);
}

// round 16
// speedup vs baseline: 1.0514x; 1.0514x over previous
#include <cuda_runtime.h>
#include <cuda_fp16.h>
#include <cstdint>

#define EPS 1e-6f

// ---------------- device scratch (no allocations allowed) ----------------
__device__ float4 g_params[4096];          // per (b,t): {1+scale, shift, gate, 0}
__device__ int    g_valid[16 * 4096];      // per batch: compacted flat indices
__device__ int    g_count[16];             // per batch: valid count
__device__ __half g_xn_h[4096 * 1024];     // normalized tokens (fp16)
__device__ float  g_featsp[2][4096 * 512]; // GEMM1 partial outputs (K-split)
__device__ __half g_u_h[65536 * 512];      // modulated-silu activations (fp16)
__device__ __half g_cn_h[65536 * 512];     // normalized chars (fp16, compacted)
__device__ __half g_wd_h[512 * 1024];      // W_down fp16
__device__ __half g_wf_h[512 * 512];       // W_fusion fp16

// ---------------- helpers ----------------
__device__ __forceinline__ float tanh_ap(float x) {
    float y;
    asm("tanh.approx.f32 %0, %1;" : "=f"(y) : "f"(x));
    return y;
}
__device__ __forceinline__ float silu_f(float z) {
    return z * (0.5f + 0.5f * tanh_ap(0.5f * z));
}
__device__ __forceinline__ uint32_t smem_u32(const void* p) {
    return (uint32_t)__cvta_generic_to_shared(p);
}
__device__ __forceinline__ void cp16(uint32_t d, const void* s) {
    asm volatile("cp.async.cg.shared.global [%0], [%1], 16;" ::"r"(d), "l"(s));
}
#define CP_COMMIT asm volatile("cp.async.commit_group;")
#define CP_WAIT0 asm volatile("cp.async.wait_group 0;")
#define CP_WAIT1 asm volatile("cp.async.wait_group 1;")

__device__ __forceinline__ void ldsm4(uint32_t& r0, uint32_t& r1, uint32_t& r2,
                                      uint32_t& r3, uint32_t addr) {
    asm volatile("ldmatrix.sync.aligned.m8n8.x4.shared.b16 {%0,%1,%2,%3}, [%4];"
                 : "=r"(r0), "=r"(r1), "=r"(r2), "=r"(r3)
                 : "r"(addr));
}
__device__ __forceinline__ void mma16(float* c, const uint32_t* a, const uint32_t* b) {
    asm volatile(
        "mma.sync.aligned.m16n8k16.row.col.f32.f16.f16.f32 "
        "{%0,%1,%2,%3}, {%4,%5,%6,%7}, {%8,%9}, {%0,%1,%2,%3};"
        : "+f"(c[0]), "+f"(c[1]), "+f"(c[2]), "+f"(c[3])
        : "r"(a[0]), "r"(a[1]), "r"(a[2]), "r"(a[3]), "r"(b[0]), "r"(b[1]));
}

// ---------------- prep bodies (merged launch) ----------------
__device__ void scan_body(const int* __restrict__ mask, int b) {
    int tid = threadIdx.x;
    int warp = tid >> 5, lane = tid & 31;
    __shared__ int wsum[8];
    const int* m = mask + b * 4096 + tid * 16;
    unsigned flags = 0;
    int cnt = 0;
#pragma unroll
    for (int i = 0; i < 16; i++)
        if (m[i] != 0) { flags |= (1u << i); cnt++; }
    int pre = cnt;
#pragma unroll
    for (int o = 1; o < 32; o <<= 1) {
        int v = __shfl_up_sync(0xffffffffu, pre, o);
        if (lane >= o) pre += v;
    }
    if (lane == 31) wsum[warp] = pre;
    __syncthreads();
    if (warp == 0) {
        int v = (lane < 8) ? wsum[lane] : 0;
#pragma unroll
        for (int o = 1; o < 8; o <<= 1) {
            int t = __shfl_up_sync(0xffffffffu, v, o);
            if (lane >= o) v += t;
        }
        if (lane < 8) wsum[lane] = v;
    }
    __syncthreads();
    int base = pre - cnt + (warp ? wsum[warp - 1] : 0);
    int ib = b * 4096;
#pragma unroll
    for (int i = 0; i < 16; i++)
        if (flags & (1u << i)) g_valid[ib + base++] = tid * 16 + i;
    if (tid == 255) g_count[b] = wsum[7];
}

__device__ void cvt_body(const float* __restrict__ Wd, const float* __restrict__ Wf,
                         int blk) {
    int i = blk * 256 + threadIdx.x;
    g_wd_h[i] = __float2half_rn(Wd[i]);
    if (i < 512 * 512) g_wf_h[i] = __float2half_rn(Wf[i]);
}

__device__ void norm_tok_body(const float* __restrict__ tok,
                              const float* __restrict__ w_pre, int blk) {
    int warp = threadIdx.x >> 5, lane = threadIdx.x & 31;
    int row = blk * 8 + warp;
    const float4* x = (const float4*)(tok + (size_t)row * 1024);
    const float4* w = (const float4*)w_pre;
    float4 v[8];
    float ss = 0.f;
#pragma unroll
    for (int i = 0; i < 8; i++) {
        float4 a = __ldcs(&x[lane + 32 * i]);
        v[i] = a;
        ss += a.x * a.x + a.y * a.y + a.z * a.z + a.w * a.w;
    }
#pragma unroll
    for (int o = 16; o >= 1; o >>= 1) ss += __shfl_xor_sync(0xffffffffu, ss, o);
    float inv = rsqrtf(ss * (1.0f / 1024.0f) + EPS);
    __half2* out = (__half2*)(g_xn_h + (size_t)row * 1024);
#pragma unroll
    for (int i = 0; i < 8; i++) {
        float4 ww = w[lane + 32 * i];
        int f4 = lane + 32 * i;
        out[2 * f4] = __floats2half2_rn(v[i].x * inv * ww.x, v[i].y * inv * ww.y);
        out[2 * f4 + 1] = __floats2half2_rn(v[i].z * inv * ww.z, v[i].w * inv * ww.w);
    }
}

// merged launch: blocks [0,16) scan, [16,2064) cvt, [2064,2576) norm_tok
__global__ __launch_bounds__(256) void k_prep(const int* __restrict__ mask,
                                              const float* __restrict__ Wd,
                                              const float* __restrict__ Wf,
                                              const float* __restrict__ tok,
                                              const float* __restrict__ w_pre) {
    int bx = blockIdx.x;
    if (bx < 16) scan_body(mask, bx);
    else if (bx < 2064) cvt_body(Wd, Wf, bx - 16);
    else norm_tok_body(tok, w_pre, bx - 2064);
}

// ---------------- fp16 GEMM core: C(128x128) += A(128xK) @ B(128xK)^T ----------------
// 256 threads = 8 warps (4M x 2N), warp tile 32x64, mma m16n8k16 f16->f32.
// smem: 3-stage ring, k-chunk 64 halfs, row stride 72 halfs (conflict-free ldmatrix).
// 2 chunks in flight (wait_group 1); one __syncthreads per 64-k chunk.
// A-fragment double buffer: ks+1's LDSM issues before ks's 16 HMMA drain.
template <int NC>
__device__ __forceinline__ void gemm_core(const __half* __restrict__ A,
                                          const __half* __restrict__ B, int lda, int ldb,
                                          int rowBase, int nBase, int kOff,
                                          float (&acc)[2][8][4], char* smraw) {
    const int STG_H = 2 * 128 * 72;
    __half* sm = (__half*)smraw;
    int tid = threadIdx.x;
    int wid = tid >> 5, lane = tid & 31;
    int warpM = wid >> 1, warpN = wid & 1;
    int r8 = lane & 7, quad = lane >> 3;

    int lrow = tid & 127;
    bool isB = tid >= 128;
    const __half* gsrc = (isB ? (B + (size_t)(nBase + lrow) * ldb)
                              : (A + (size_t)(rowBase + lrow) * lda)) + kOff;
    uint32_t sdst0 = smem_u32(sm) + (uint32_t)(((isB ? 128 * 72 : 0) + lrow * 72) * 2);

#define STAGE_LD(s, buf)                                                     \
    do {                                                                     \
        const __half* gp = gsrc + (s)*64;                                    \
        uint32_t sp = sdst0 + (uint32_t)((buf)*STG_H * 2);                   \
        _Pragma("unroll") for (int j = 0; j < 8; j++) cp16(sp + j * 16, gp + j * 8); \
        CP_COMMIT;                                                           \
    } while (0)

    STAGE_LD(0, 0);
    STAGE_LD(1, 1);

    uint32_t sbase = smem_u32(sm);
    int arow = warpM * 32 + ((quad & 1) << 3) + r8;
    int aco = (quad >> 1) << 3;
    int brow = warpN * 64 + ((quad >> 1) << 3) + r8;
    int bco = (quad & 1) << 3;

    int cur = 0, nxt = 2;
    for (int kc = 0; kc < NC; kc++) {
        if (kc < NC - 1) { CP_WAIT1; }
        else { CP_WAIT0; }
        __syncthreads();
        if (kc + 2 < NC) STAGE_LD(kc + 2, nxt);

        uint32_t stg = sbase + (uint32_t)((cur * STG_H) * 2);
        uint32_t astg = stg, bstg = stg + (uint32_t)(128 * 72 * 2);

        uint32_t af[2][2][4];  // [buf][mt][4] double-buffered A frags
#pragma unroll
        for (int mt = 0; mt < 2; mt++) {
            uint32_t addr = astg + (uint32_t)(((arow + mt * 16) * 72 + aco) * 2);
            ldsm4(af[0][mt][0], af[0][mt][1], af[0][mt][2], af[0][mt][3], addr);
        }
#pragma unroll
        for (int ks = 0; ks < 4; ks++) {
            int k0 = ks * 16;
            if (ks < 3) {
#pragma unroll
                for (int mt = 0; mt < 2; mt++) {
                    uint32_t addr =
                        astg + (uint32_t)(((arow + mt * 16) * 72 + aco + k0 + 16) * 2);
                    ldsm4(af[(ks + 1) & 1][mt][0], af[(ks + 1) & 1][mt][1],
                          af[(ks + 1) & 1][mt][2], af[(ks + 1) & 1][mt][3], addr);
                }
            }
            const uint32_t(*ac)[4] = af[ks & 1];
#pragma unroll
            for (int g16 = 0; g16 < 4; g16++) {
                uint32_t b0, b1, b2, b3;
                uint32_t addr = bstg + (uint32_t)(((brow + g16 * 16) * 72 + bco + k0) * 2);
                ldsm4(b0, b1, b2, b3, addr);
                uint32_t bf0[2] = {b0, b1}, bf1[2] = {b2, b3};
                mma16(acc[0][g16 * 2], ac[0], bf0);
                mma16(acc[0][g16 * 2 + 1], ac[0], bf1);
                mma16(acc[1][g16 * 2], ac[1], bf0);
                mma16(acc[1][g16 * 2 + 1], ac[1], bf1);
            }
        }
        cur = (cur == 2) ? 0 : cur + 1;
        nxt = (nxt == 2) ? 0 : nxt + 1;
    }
#undef STAGE_LD
}

// ---------------- kernel 2: GEMM1 (K-split x2) partials ----------------
__global__ __launch_bounds__(256, 2) void k_gemm1() {
    extern __shared__ char smraw[];
    float acc[2][8][4] = {};
    int split = blockIdx.x & 1;
    int nTile = (blockIdx.x >> 1) & 3;
    int rowTile = blockIdx.x >> 3;
    gemm_core<8>(g_xn_h, g_wd_h, 1024, 1024, rowTile * 128, nTile * 128, split * 512,
                 acc, smraw);
    float* dst = g_featsp[split];
    int tid = threadIdx.x, wid = tid >> 5, lane = tid & 31;
    int warpM = wid >> 1, warpN = wid & 1, g = lane >> 2, qc = lane & 3;
#pragma unroll
    for (int mi = 0; mi < 2; mi++)
#pragma unroll
        for (int ni = 0; ni < 8; ni++) {
            int r = rowTile * 128 + warpM * 32 + mi * 16 + g;
            int c = nTile * 128 + warpN * 64 + ni * 8 + qc * 2;
            float2 v0 = {acc[mi][ni][0], acc[mi][ni][1]};
            float2 v1 = {acc[mi][ni][2], acc[mi][ni][3]};
            *(float2*)(dst + (size_t)r * 512 + c) = v0;
            *(float2*)(dst + (size_t)(r + 8) * 512 + c) = v1;
        }
}

// ---------------- kernel 3: sum partials + rmsnorm + silu + W_proj -> params --------
__global__ __launch_bounds__(256) void k_post(const float* __restrict__ w_tok,
                                              const float* __restrict__ Wp) {
    int warp = threadIdx.x >> 5, lane = threadIdx.x & 31;
    int row = blockIdx.x * 8 + warp;
    const float4* f0 = (const float4*)(g_featsp[0] + (size_t)row * 512);
    const float4* f1 = (const float4*)(g_featsp[1] + (size_t)row * 512);
    float4 v[4];
    float ss = 0.f;
#pragma unroll
    for (int i = 0; i < 4; i++) {
        float4 a = __ldcs(&f0[lane + 32 * i]);
        float4 b = __ldcs(&f1[lane + 32 * i]);
        a.x += b.x; a.y += b.y; a.z += b.z; a.w += b.w;
        v[i] = a;
        ss += a.x * a.x + a.y * a.y + a.z * a.z + a.w * a.w;
    }
#pragma unroll
    for (int o = 16; o >= 1; o >>= 1) ss += __shfl_xor_sync(0xffffffffu, ss, o);
    float inv = rsqrtf(ss * (1.0f / 512.0f) + EPS);
    const float4* wt = (const float4*)w_tok;
    const float4* wp0 = (const float4*)Wp;
    const float4* wp1 = (const float4*)(Wp + 512);
    const float4* wp2 = (const float4*)(Wp + 1024);
    float p0 = 0.f, p1 = 0.f, p2 = 0.f;
#pragma unroll
    for (int i = 0; i < 4; i++) {
        float4 ww = wt[lane + 32 * i];
        float4 a = v[i];
        float s0 = silu_f(a.x * inv * ww.x), s1 = silu_f(a.y * inv * ww.y);
        float s2 = silu_f(a.z * inv * ww.z), s3 = silu_f(a.w * inv * ww.w);
        float4 q0 = wp0[lane + 32 * i], q1 = wp1[lane + 32 * i], q2 = wp2[lane + 32 * i];
        p0 += s0 * q0.x + s1 * q0.y + s2 * q0.z + s3 * q0.w;
        p1 += s0 * q1.x + s1 * q1.y + s2 * q1.z + s3 * q1.w;
        p2 += s0 * q2.x + s1 * q2.y + s2 * q2.z + s3 * q2.w;
    }
#pragma unroll
    for (int o = 16; o >= 1; o >>= 1) {
        p0 += __shfl_xor_sync(0xffffffffu, p0, o);
        p1 += __shfl_xor_sync(0xffffffffu, p1, o);
        p2 += __shfl_xor_sync(0xffffffffu, p2, o);
    }
    if (lane == 0) {
        float4 pr;
        pr.x = 1.0f + p0;
        pr.y = p1;
        pr.z = 1.0f / (1.0f + __expf(-p2));
        pr.w = 0.f;
        g_params[row] = pr;
    }
}

// ---------------- kernel 4: char rmsnorm + modulated silu -> g_u_h, g_cn_h ----------
__global__ __launch_bounds__(256) void k_norm_char(const float* __restrict__ ch,
                                                   const float* __restrict__ w_char) {
    int warp = threadIdx.x >> 5, lane = threadIdx.x & 31;
    int jj = blockIdx.x * 8 + warp;
    int b = jj >> 12, j = jj & 4095;
    if (j >= g_count[b]) return;
    int flat = g_valid[b * 4096 + j];
    float4 p = g_params[b * 256 + (flat >> 4)];
    const float4* x = (const float4*)(ch + (size_t)(b * 4096 + flat) * 512);
    float4 v[4];
    float ss = 0.f;
#pragma unroll
    for (int i = 0; i < 4; i++) {
        float4 a = __ldcs(&x[lane + 32 * i]);
        v[i] = a;
        ss += a.x * a.x + a.y * a.y + a.z * a.z + a.w * a.w;
    }
#pragma unroll
    for (int o = 16; o >= 1; o >>= 1) ss += __shfl_xor_sync(0xffffffffu, ss, o);
    float inv = rsqrtf(ss * (1.0f / 512.0f) + EPS);
    const float4* w = (const float4*)w_char;
    __half2* uo = (__half2*)(g_u_h + (size_t)(b * 4096 + j) * 512);
    __half2* co = (__half2*)(g_cn_h + (size_t)(b * 4096 + j) * 512);
#pragma unroll
    for (int i = 0; i < 4; i++) {
        float4 ww = w[lane + 32 * i];
        float4 a = v[i];
        float c0 = a.x * inv * ww.x, c1 = a.y * inv * ww.y;
        float c2 = a.z * inv * ww.z, c3 = a.w * inv * ww.w;
        int f4 = lane + 32 * i;
        co[2 * f4] = __floats2half2_rn(c0, c1);
        co[2 * f4 + 1] = __floats2half2_rn(c2, c3);
        uo[2 * f4] = __floats2half2_rn(silu_f(c0 * p.x + p.y), silu_f(c1 * p.x + p.y));
        uo[2 * f4 + 1] = __floats2half2_rn(silu_f(c2 * p.x + p.y), silu_f(c3 * p.x + p.y));
    }
}

// ---------------- kernel 5: GEMM2 + gated mix + filler epilogue ----------------
__global__ __launch_bounds__(256, 2) void k_gemm_fuse(const float* __restrict__ filler,
                                                      float* __restrict__ out) {
    int rowTile = blockIdx.x >> 2, nTile = blockIdx.x & 3;
    int b = rowTile >> 5, j0 = (rowTile & 31) * 128;
    int cnt = g_count[b];
    int tid = threadIdx.x;

    if (j0 >= cnt) {  // entire tile filler: broadcast
        int f4c = tid & 31, r0 = tid >> 5;
        float4 fv = ((const float4*)filler)[nTile * 32 + f4c];
        float4* ob = (float4*)(out + (size_t)(b * 4096 + j0) * 512 + nTile * 128);
#pragma unroll
        for (int it = 0; it < 16; it++) __stcs(&ob[(size_t)(r0 + 8 * it) * 128 + f4c], fv);
        return;
    }

    int wid = tid >> 5, lane = tid & 31;
    int warpM = wid >> 1, warpN = wid & 1, g = lane >> 2, qc = lane & 3;

    // prefetch epilogue metadata (gate/valid for this thread's 4 rows) BEFORE the
    // GEMM so the dependent g_valid->g_params chain is off the kernel tail.
    float gate_r[4];
    bool val_r[4];
#pragma unroll
    for (int mi = 0; mi < 2; mi++)
#pragma unroll
        for (int rr = 0; rr < 2; rr++) {
            int j = j0 + warpM * 32 + mi * 16 + g + rr * 8;
            bool v = j < cnt;
            val_r[mi * 2 + rr] = v;
            float gt = 0.f;
            if (v) {
                int flat = g_valid[b * 4096 + j];
                gt = g_params[b * 256 + (flat >> 4)].z;
            }
            gate_r[mi * 2 + rr] = gt;
        }

    extern __shared__ char smraw[];
    float acc[2][8][4] = {};
    gemm_core<8>(g_u_h, g_wf_h, 512, 512, b * 4096 + j0, nTile * 128, 0, acc, smraw);

    const float2* fil2 = (const float2*)filler;
#pragma unroll
    for (int mi = 0; mi < 2; mi++)
#pragma unroll
        for (int rr = 0; rr < 2; rr++) {
            int idx = mi * 2 + rr;
            int j = j0 + warpM * 32 + mi * 16 + g + rr * 8;
            float gate = gate_r[idx];
            float og = 1.f - gate;
            const __half2* cnrow = (const __half2*)(g_cn_h + (size_t)(b * 4096 + j) * 512);
            float* orow = out + (size_t)(b * 4096 + j) * 512;
#pragma unroll
            for (int ni = 0; ni < 8; ni++) {
                int c = nTile * 128 + warpN * 64 + ni * 8 + qc * 2;
                float a0 = acc[mi][ni][rr * 2 + 0], a1 = acc[mi][ni][rr * 2 + 1];
                float2 o;
                if (val_r[idx]) {
                    float2 cv = __half22float2(cnrow[c >> 1]);
                    o.x = gate * a0 + og * cv.x;
                    o.y = gate * a1 + og * cv.y;
                } else {
                    o = fil2[c >> 1];
                }
                __stcs((float2*)(orow + c), o);
            }
        }
}

// ---------------- launch ----------------
extern "C" void kernel_launch(void* const* d_in, const int* in_sizes, int n_in,
                              void* d_out, int out_size) {
    (void)in_sizes;
    (void)n_in;
    (void)out_size;
    const float* tok = (const float*)d_in[0];
    const float* ch = (const float*)d_in[2];
    const int* cmask = (const int*)d_in[3];
    const float* filler = (const float*)d_in[4];
    const float* w_pre = (const float*)d_in[5];
    const float* w_tok = (const float*)d_in[6];
    const float* w_char = (const float*)d_in[7];
    const float* Wd = (const float*)d_in[8];
    const float* Wp = (const float*)d_in[9];
    const float* Wf = (const float*)d_in[10];
    float* out = (float*)d_out;

    const int SMEM = 3 * 2 * 128 * 72 * 2;  // 110592 bytes -> 2 CTAs/SM
    cudaFuncSetAttribute(k_gemm1, cudaFuncAttributeMaxDynamicSharedMemorySize, SMEM);
    cudaFuncSetAttribute(k_gemm_fuse, cudaFuncAttributeMaxDynamicSharedMemorySize, SMEM);

    k_prep<<<2576, 256>>>(cmask, Wd, Wf, tok, w_pre);
    k_gemm1<<<256, 256, SMEM>>>();
    k_post<<<512, 256>>>(w_tok, Wp);
    k_norm_char<<<8192, 256>>>(ch, w_char);
    k_gemm_fuse<<<2048, 256, SMEM>>>(filler, out);
}

// round 17
// speedup vs baseline: 1.0652x; 1.0131x over previous
#include <cuda_runtime.h>
#include <cuda_fp16.h>
#include <cstdint>

#define EPS 1e-6f

// ---------------- device scratch (no allocations allowed) ----------------
__device__ float4 g_params[4096];          // per (b,t): {1+scale, shift, gate, 0}
__device__ int    g_valid[16 * 4096];      // per batch: compacted flat indices
__device__ int    g_count[16];             // per batch: valid count
__device__ __half g_xn_h[4096 * 1024];     // normalized tokens (fp16)
__device__ float  g_featsp[2][4096 * 512]; // GEMM1 partial outputs (K-split)
__device__ __half g_u_h[65536 * 512];      // modulated-silu activations (fp16)
__device__ __half g_cn_h[65536 * 512];     // normalized chars (fp16, compacted)
__device__ __half g_wd_h[512 * 1024];      // W_down fp16
__device__ __half g_wf_h[512 * 512];       // W_fusion fp16

// ---------------- helpers ----------------
__device__ __forceinline__ float tanh_ap(float x) {
    float y;
    asm("tanh.approx.f32 %0, %1;" : "=f"(y) : "f"(x));
    return y;
}
__device__ __forceinline__ float silu_f(float z) {
    return z * (0.5f + 0.5f * tanh_ap(0.5f * z));
}
__device__ __forceinline__ uint32_t smem_u32(const void* p) {
    return (uint32_t)__cvta_generic_to_shared(p);
}
__device__ __forceinline__ uint32_t h2u(__half2 h) {
    return *(uint32_t*)&h;
}
__device__ __forceinline__ void cp16(uint32_t d, const void* s) {
    asm volatile("cp.async.cg.shared.global [%0], [%1], 16;" ::"r"(d), "l"(s));
}
#define CP_COMMIT asm volatile("cp.async.commit_group;")
#define CP_WAIT0 asm volatile("cp.async.wait_group 0;")
#define CP_WAIT1 asm volatile("cp.async.wait_group 1;")

__device__ __forceinline__ void ldsm4(uint32_t& r0, uint32_t& r1, uint32_t& r2,
                                      uint32_t& r3, uint32_t addr) {
    asm volatile("ldmatrix.sync.aligned.m8n8.x4.shared.b16 {%0,%1,%2,%3}, [%4];"
                 : "=r"(r0), "=r"(r1), "=r"(r2), "=r"(r3)
                 : "r"(addr));
}
__device__ __forceinline__ void mma16(float* c, const uint32_t* a, const uint32_t* b) {
    asm volatile(
        "mma.sync.aligned.m16n8k16.row.col.f32.f16.f16.f32 "
        "{%0,%1,%2,%3}, {%4,%5,%6,%7}, {%8,%9}, {%0,%1,%2,%3};"
        : "+f"(c[0]), "+f"(c[1]), "+f"(c[2]), "+f"(c[3])
        : "r"(a[0]), "r"(a[1]), "r"(a[2]), "r"(a[3]), "r"(b[0]), "r"(b[1]));
}

// ---------------- prep bodies (merged launch) ----------------
__device__ void scan_body(const int* __restrict__ mask, int b) {
    int tid = threadIdx.x;
    int warp = tid >> 5, lane = tid & 31;
    __shared__ int wsum[8];
    const int* m = mask + b * 4096 + tid * 16;
    unsigned flags = 0;
    int cnt = 0;
#pragma unroll
    for (int i = 0; i < 16; i++)
        if (m[i] != 0) { flags |= (1u << i); cnt++; }
    int pre = cnt;
#pragma unroll
    for (int o = 1; o < 32; o <<= 1) {
        int v = __shfl_up_sync(0xffffffffu, pre, o);
        if (lane >= o) pre += v;
    }
    if (lane == 31) wsum[warp] = pre;
    __syncthreads();
    if (warp == 0) {
        int v = (lane < 8) ? wsum[lane] : 0;
#pragma unroll
        for (int o = 1; o < 8; o <<= 1) {
            int t = __shfl_up_sync(0xffffffffu, v, o);
            if (lane >= o) v += t;
        }
        if (lane < 8) wsum[lane] = v;
    }
    __syncthreads();
    int base = pre - cnt + (warp ? wsum[warp - 1] : 0);
    int ib = b * 4096;
#pragma unroll
    for (int i = 0; i < 16; i++)
        if (flags & (1u << i)) g_valid[ib + base++] = tid * 16 + i;
    if (tid == 255) g_count[b] = wsum[7];
}

// vectorized: one float4 (4 weights) per thread per block index
__device__ void cvt_body(const float* __restrict__ Wd, const float* __restrict__ Wf,
                         int blk) {
    int i4 = blk * 256 + threadIdx.x;  // float4 index, < 131072
    float4 w = ((const float4*)Wd)[i4];
    __half2 h0 = __floats2half2_rn(w.x, w.y);
    __half2 h1 = __floats2half2_rn(w.z, w.w);
    *(uint2*)(g_wd_h + 4 * (size_t)i4) = make_uint2(h2u(h0), h2u(h1));
    if (i4 < 65536) {
        float4 v = ((const float4*)Wf)[i4];
        __half2 g0 = __floats2half2_rn(v.x, v.y);
        __half2 g1 = __floats2half2_rn(v.z, v.w);
        *(uint2*)(g_wf_h + 4 * (size_t)i4) = make_uint2(h2u(g0), h2u(g1));
    }
}

__device__ void norm_tok_body(const float* __restrict__ tok,
                              const float* __restrict__ w_pre, int blk) {
    int warp = threadIdx.x >> 5, lane = threadIdx.x & 31;
    int row = blk * 8 + warp;
    const float4* x = (const float4*)(tok + (size_t)row * 1024);
    const float4* w = (const float4*)w_pre;
    float4 v[8];
    float ss = 0.f;
#pragma unroll
    for (int i = 0; i < 8; i++) {
        float4 a = __ldcs(&x[lane + 32 * i]);
        v[i] = a;
        ss += a.x * a.x + a.y * a.y + a.z * a.z + a.w * a.w;
    }
#pragma unroll
    for (int o = 16; o >= 1; o >>= 1) ss += __shfl_xor_sync(0xffffffffu, ss, o);
    float inv = rsqrtf(ss * (1.0f / 1024.0f) + EPS);
    __half* out = g_xn_h + (size_t)row * 1024;
#pragma unroll
    for (int i = 0; i < 8; i++) {
        float4 ww = w[lane + 32 * i];
        int f4 = lane + 32 * i;
        __half2 h0 = __floats2half2_rn(v[i].x * inv * ww.x, v[i].y * inv * ww.y);
        __half2 h1 = __floats2half2_rn(v[i].z * inv * ww.z, v[i].w * inv * ww.w);
        *(uint2*)(out + 4 * f4) = make_uint2(h2u(h0), h2u(h1));
    }
}

// merged launch: blocks [0,16) scan, [16,528) cvt, [528,1040) norm_tok
__global__ __launch_bounds__(256) void k_prep(const int* __restrict__ mask,
                                              const float* __restrict__ Wd,
                                              const float* __restrict__ Wf,
                                              const float* __restrict__ tok,
                                              const float* __restrict__ w_pre) {
    int bx = blockIdx.x;
    if (bx < 16) scan_body(mask, bx);
    else if (bx < 528) cvt_body(Wd, Wf, bx - 16);
    else norm_tok_body(tok, w_pre, bx - 528);
}

// ---------------- fp16 GEMM core: C(128x128) += A(128xK) @ B(128xK)^T ----------------
// 256 threads = 8 warps (4M x 2N), warp tile 32x64, mma m16n8k16 f16->f32.
// smem: 3-stage ring, k-chunk 64 halfs, row stride 72 halfs (conflict-free ldmatrix).
// 2 chunks in flight (wait_group 1); one __syncthreads per 64-k chunk.
// A-fragment double buffer: ks+1's LDSM issues before ks's 16 HMMA drain.
template <int NC>
__device__ __forceinline__ void gemm_core(const __half* __restrict__ A,
                                          const __half* __restrict__ B, int lda, int ldb,
                                          int rowBase, int nBase, int kOff,
                                          float (&acc)[2][8][4], char* smraw) {
    const int STG_H = 2 * 128 * 72;
    __half* sm = (__half*)smraw;
    int tid = threadIdx.x;
    int wid = tid >> 5, lane = tid & 31;
    int warpM = wid >> 1, warpN = wid & 1;
    int r8 = lane & 7, quad = lane >> 3;

    int lrow = tid & 127;
    bool isB = tid >= 128;
    const __half* gsrc = (isB ? (B + (size_t)(nBase + lrow) * ldb)
                              : (A + (size_t)(rowBase + lrow) * lda)) + kOff;
    uint32_t sdst0 = smem_u32(sm) + (uint32_t)(((isB ? 128 * 72 : 0) + lrow * 72) * 2);

#define STAGE_LD(s, buf)                                                     \
    do {                                                                     \
        const __half* gp = gsrc + (s)*64;                                    \
        uint32_t sp = sdst0 + (uint32_t)((buf)*STG_H * 2);                   \
        _Pragma("unroll") for (int j = 0; j < 8; j++) cp16(sp + j * 16, gp + j * 8); \
        CP_COMMIT;                                                           \
    } while (0)

    STAGE_LD(0, 0);
    STAGE_LD(1, 1);

    uint32_t sbase = smem_u32(sm);
    int arow = warpM * 32 + ((quad & 1) << 3) + r8;
    int aco = (quad >> 1) << 3;
    int brow = warpN * 64 + ((quad >> 1) << 3) + r8;
    int bco = (quad & 1) << 3;

    int cur = 0, nxt = 2;
    for (int kc = 0; kc < NC; kc++) {
        if (kc < NC - 1) { CP_WAIT1; }
        else { CP_WAIT0; }
        __syncthreads();
        if (kc + 2 < NC) STAGE_LD(kc + 2, nxt);

        uint32_t stg = sbase + (uint32_t)((cur * STG_H) * 2);
        uint32_t astg = stg, bstg = stg + (uint32_t)(128 * 72 * 2);

        uint32_t af[2][2][4];  // [buf][mt][4] double-buffered A frags
#pragma unroll
        for (int mt = 0; mt < 2; mt++) {
            uint32_t addr = astg + (uint32_t)(((arow + mt * 16) * 72 + aco) * 2);
            ldsm4(af[0][mt][0], af[0][mt][1], af[0][mt][2], af[0][mt][3], addr);
        }
#pragma unroll
        for (int ks = 0; ks < 4; ks++) {
            int k0 = ks * 16;
            if (ks < 3) {
#pragma unroll
                for (int mt = 0; mt < 2; mt++) {
                    uint32_t addr =
                        astg + (uint32_t)(((arow + mt * 16) * 72 + aco + k0 + 16) * 2);
                    ldsm4(af[(ks + 1) & 1][mt][0], af[(ks + 1) & 1][mt][1],
                          af[(ks + 1) & 1][mt][2], af[(ks + 1) & 1][mt][3], addr);
                }
            }
            const uint32_t(*ac)[4] = af[ks & 1];
#pragma unroll
            for (int g16 = 0; g16 < 4; g16++) {
                uint32_t b0, b1, b2, b3;
                uint32_t addr = bstg + (uint32_t)(((brow + g16 * 16) * 72 + bco + k0) * 2);
                ldsm4(b0, b1, b2, b3, addr);
                uint32_t bf0[2] = {b0, b1}, bf1[2] = {b2, b3};
                mma16(acc[0][g16 * 2], ac[0], bf0);
                mma16(acc[0][g16 * 2 + 1], ac[0], bf1);
                mma16(acc[1][g16 * 2], ac[1], bf0);
                mma16(acc[1][g16 * 2 + 1], ac[1], bf1);
            }
        }
        cur = (cur == 2) ? 0 : cur + 1;
        nxt = (nxt == 2) ? 0 : nxt + 1;
    }
#undef STAGE_LD
}

// ---------------- kernel 2: GEMM1 (K-split x2) partials ----------------
__global__ __launch_bounds__(256, 2) void k_gemm1() {
    extern __shared__ char smraw[];
    float acc[2][8][4] = {};
    int split = blockIdx.x & 1;
    int nTile = (blockIdx.x >> 1) & 3;
    int rowTile = blockIdx.x >> 3;
    gemm_core<8>(g_xn_h, g_wd_h, 1024, 1024, rowTile * 128, nTile * 128, split * 512,
                 acc, smraw);
    float* dst = g_featsp[split];
    int tid = threadIdx.x, wid = tid >> 5, lane = tid & 31;
    int warpM = wid >> 1, warpN = wid & 1, g = lane >> 2, qc = lane & 3;
#pragma unroll
    for (int mi = 0; mi < 2; mi++)
#pragma unroll
        for (int ni = 0; ni < 8; ni++) {
            int r = rowTile * 128 + warpM * 32 + mi * 16 + g;
            int c = nTile * 128 + warpN * 64 + ni * 8 + qc * 2;
            float2 v0 = {acc[mi][ni][0], acc[mi][ni][1]};
            float2 v1 = {acc[mi][ni][2], acc[mi][ni][3]};
            *(float2*)(dst + (size_t)r * 512 + c) = v0;
            *(float2*)(dst + (size_t)(r + 8) * 512 + c) = v1;
        }
}

// ---------------- kernel 3: sum partials + rmsnorm + silu + W_proj -> params --------
__global__ __launch_bounds__(256) void k_post(const float* __restrict__ w_tok,
                                              const float* __restrict__ Wp) {
    int warp = threadIdx.x >> 5, lane = threadIdx.x & 31;
    int row = blockIdx.x * 8 + warp;
    const float4* f0 = (const float4*)(g_featsp[0] + (size_t)row * 512);
    const float4* f1 = (const float4*)(g_featsp[1] + (size_t)row * 512);
    float4 v[4];
    float ss = 0.f;
#pragma unroll
    for (int i = 0; i < 4; i++) {
        float4 a = f0[lane + 32 * i];
        float4 b = f1[lane + 32 * i];
        a.x += b.x; a.y += b.y; a.z += b.z; a.w += b.w;
        v[i] = a;
        ss += a.x * a.x + a.y * a.y + a.z * a.z + a.w * a.w;
    }
#pragma unroll
    for (int o = 16; o >= 1; o >>= 1) ss += __shfl_xor_sync(0xffffffffu, ss, o);
    float inv = rsqrtf(ss * (1.0f / 512.0f) + EPS);
    const float4* wt = (const float4*)w_tok;
    const float4* wp0 = (const float4*)Wp;
    const float4* wp1 = (const float4*)(Wp + 512);
    const float4* wp2 = (const float4*)(Wp + 1024);
    float p0 = 0.f, p1 = 0.f, p2 = 0.f;
#pragma unroll
    for (int i = 0; i < 4; i++) {
        float4 ww = wt[lane + 32 * i];
        float4 a = v[i];
        float s0 = silu_f(a.x * inv * ww.x), s1 = silu_f(a.y * inv * ww.y);
        float s2 = silu_f(a.z * inv * ww.z), s3 = silu_f(a.w * inv * ww.w);
        float4 q0 = wp0[lane + 32 * i], q1 = wp1[lane + 32 * i], q2 = wp2[lane + 32 * i];
        p0 += s0 * q0.x + s1 * q0.y + s2 * q0.z + s3 * q0.w;
        p1 += s0 * q1.x + s1 * q1.y + s2 * q1.z + s3 * q1.w;
        p2 += s0 * q2.x + s1 * q2.y + s2 * q2.z + s3 * q2.w;
    }
#pragma unroll
    for (int o = 16; o >= 1; o >>= 1) {
        p0 += __shfl_xor_sync(0xffffffffu, p0, o);
        p1 += __shfl_xor_sync(0xffffffffu, p1, o);
        p2 += __shfl_xor_sync(0xffffffffu, p2, o);
    }
    if (lane == 0) {
        float4 pr;
        pr.x = 1.0f + p0;
        pr.y = p1;
        pr.z = 1.0f / (1.0f + __expf(-p2));
        pr.w = 0.f;
        g_params[row] = pr;
    }
}

// ---------------- kernel 4: char rmsnorm + modulated silu -> g_u_h, g_cn_h ----------
__global__ __launch_bounds__(256) void k_norm_char(const float* __restrict__ ch,
                                                   const float* __restrict__ w_char) {
    int warp = threadIdx.x >> 5, lane = threadIdx.x & 31;
    int jj = blockIdx.x * 8 + warp;
    int b = jj >> 12, j = jj & 4095;
    if (j >= g_count[b]) return;
    int flat = g_valid[b * 4096 + j];
    float4 p = g_params[b * 256 + (flat >> 4)];
    const float4* x = (const float4*)(ch + (size_t)(b * 4096 + flat) * 512);
    float4 v[4];
    float ss = 0.f;
#pragma unroll
    for (int i = 0; i < 4; i++) {
        float4 a = __ldcs(&x[lane + 32 * i]);
        v[i] = a;
        ss += a.x * a.x + a.y * a.y + a.z * a.z + a.w * a.w;
    }
#pragma unroll
    for (int o = 16; o >= 1; o >>= 1) ss += __shfl_xor_sync(0xffffffffu, ss, o);
    float inv = rsqrtf(ss * (1.0f / 512.0f) + EPS);
    const float4* w = (const float4*)w_char;
    __half* uo = g_u_h + (size_t)(b * 4096 + j) * 512;
    __half* co = g_cn_h + (size_t)(b * 4096 + j) * 512;
#pragma unroll
    for (int i = 0; i < 4; i++) {
        float4 ww = w[lane + 32 * i];
        float4 a = v[i];
        float c0 = a.x * inv * ww.x, c1 = a.y * inv * ww.y;
        float c2 = a.z * inv * ww.z, c3 = a.w * inv * ww.w;
        int f4 = lane + 32 * i;
        __half2 cc0 = __floats2half2_rn(c0, c1);
        __half2 cc1 = __floats2half2_rn(c2, c3);
        *(uint2*)(co + 4 * f4) = make_uint2(h2u(cc0), h2u(cc1));
        __half2 uu0 = __floats2half2_rn(silu_f(c0 * p.x + p.y), silu_f(c1 * p.x + p.y));
        __half2 uu1 = __floats2half2_rn(silu_f(c2 * p.x + p.y), silu_f(c3 * p.x + p.y));
        *(uint2*)(uo + 4 * f4) = make_uint2(h2u(uu0), h2u(uu1));
    }
}

// ---------------- kernel 5: GEMM2 + gated mix + filler epilogue ----------------
__global__ __launch_bounds__(256, 2) void k_gemm_fuse(const float* __restrict__ filler,
                                                      float* __restrict__ out) {
    int rowTile = blockIdx.x >> 2, nTile = blockIdx.x & 3;
    int b = rowTile >> 5, j0 = (rowTile & 31) * 128;
    int cnt = g_count[b];
    int tid = threadIdx.x;

    if (j0 >= cnt) {  // entire tile filler: broadcast
        int f4c = tid & 31, r0 = tid >> 5;
        float4 fv = ((const float4*)filler)[nTile * 32 + f4c];
        float4* ob = (float4*)(out + (size_t)(b * 4096 + j0) * 512 + nTile * 128);
#pragma unroll
        for (int it = 0; it < 16; it++) __stcs(&ob[(size_t)(r0 + 8 * it) * 128 + f4c], fv);
        return;
    }

    extern __shared__ char smraw[];
    float acc[2][8][4] = {};
    gemm_core<8>(g_u_h, g_wf_h, 512, 512, b * 4096 + j0, nTile * 128, 0, acc, smraw);

    int wid = tid >> 5, lane = tid & 31;
    int warpM = wid >> 1, warpN = wid & 1, g = lane >> 2, qc = lane & 3;
    const float2* fil2 = (const float2*)filler;
#pragma unroll
    for (int mi = 0; mi < 2; mi++)
#pragma unroll
        for (int rr = 0; rr < 2; rr++) {
            int lr = warpM * 32 + mi * 16 + g + rr * 8;
            int j = j0 + lr;
            bool val = j < cnt;
            float gate = 0.f;
            if (val) {
                int flat = g_valid[b * 4096 + j];
                gate = g_params[b * 256 + (flat >> 4)].z;
            }
            float og = 1.f - gate;
            const __half2* cnrow = (const __half2*)(g_cn_h + (size_t)(b * 4096 + j) * 512);
            float* orow = out + (size_t)(b * 4096 + j) * 512;
#pragma unroll
            for (int ni = 0; ni < 8; ni++) {
                int c = nTile * 128 + warpN * 64 + ni * 8 + qc * 2;
                float a0 = acc[mi][ni][rr * 2 + 0], a1 = acc[mi][ni][rr * 2 + 1];
                float2 o;
                if (val) {
                    float2 cv = __half22float2(cnrow[c >> 1]);
                    o.x = gate * a0 + og * cv.x;
                    o.y = gate * a1 + og * cv.y;
                } else {
                    o = fil2[c >> 1];
                }
                __stcs((float2*)(orow + c), o);
            }
        }
}

// ---------------- launch ----------------
extern "C" void kernel_launch(void* const* d_in, const int* in_sizes, int n_in,
                              void* d_out, int out_size) {
    (void)in_sizes;
    (void)n_in;
    (void)out_size;
    const float* tok = (const float*)d_in[0];
    const float* ch = (const float*)d_in[2];
    const int* cmask = (const int*)d_in[3];
    const float* filler = (const float*)d_in[4];
    const float* w_pre = (const float*)d_in[5];
    const float* w_tok = (const float*)d_in[6];
    const float* w_char = (const float*)d_in[7];
    const float* Wd = (const float*)d_in[8];
    const float* Wp = (const float*)d_in[9];
    const float* Wf = (const float*)d_in[10];
    float* out = (float*)d_out;

    const int SMEM = 3 * 2 * 128 * 72 * 2;  // 110592 bytes -> 2 CTAs/SM
    cudaFuncSetAttribute(k_gemm1, cudaFuncAttributeMaxDynamicSharedMemorySize, SMEM);
    cudaFuncSetAttribute(k_gemm_fuse, cudaFuncAttributeMaxDynamicSharedMemorySize, SMEM);

    k_prep<<<1040, 256>>>(cmask, Wd, Wf, tok, w_pre);
    k_gemm1<<<256, 256, SMEM>>>();
    k_post<<<512, 256>>>(w_tok, Wp);
    k_norm_char<<<8192, 256>>>(ch, w_char);
    k_gemm_fuse<<<2048, 256, SMEM>>>(filler, out);
}